// round 2
// baseline (speedup 1.0000x reference)
#include <cuda_runtime.h>
#include <cuda_bf16.h>
#include <cstdint>

#define NN   50000
#define NE   800000
#define DIN  64
#define EIN  32
#define KE   160    // 2*DIN + EIN
#define HID  128
#define EOUT 64
#define DOUT 64

// ---------------- scratch (static device globals; no allocation) ----------------
__device__ unsigned g_segmax[NN];          // monotone-key-encoded float max
__device__ float    g_denom[NN];
__device__ float    g_agg[(size_t)NN * EOUT];
__device__ float    g_logit[NE];
__device__ float    g_ex[NE];

// float <-> order-preserving unsigned key
__device__ __forceinline__ unsigned fkey(float f) {
    int i = __float_as_int(f);
    return (i >= 0) ? (unsigned(i) | 0x80000000u) : ~unsigned(i);
}
__device__ __forceinline__ float funkey(unsigned k) {
    int i = (k & 0x80000000u) ? int(k & 0x7fffffffu) : ~int(k);
    return __int_as_float(i);
}

// ---------------------------------------------------------------------------
// layer1: sH[64][128] = relu(sX[64][K] @ W[K][128] + bias)
// 256 threads; microtile 8m x 4n per thread.
// ---------------------------------------------------------------------------
template <int K>
__device__ __forceinline__ void layer1_tile(
    const float* __restrict__ W,      // global [K][128]
    const float* __restrict__ sX,     // shared [64][K]
    float* __restrict__ sW,           // shared buffer >= 32*128 floats
    float* __restrict__ sH,           // shared [64][128]
    const float* __restrict__ sB,     // shared [128]
    int t)
{
    const int nb = t & 31, mb = t >> 5;
    const int n0 = nb * 4, m0 = mb * 8;
    float acc[8][4];
#pragma unroll
    for (int i = 0; i < 8; i++)
#pragma unroll
        for (int j = 0; j < 4; j++) acc[i][j] = 0.f;

    for (int kc = 0; kc < K; kc += 32) {
        __syncthreads();  // previous users of sW done
#pragma unroll
        for (int i = 0; i < 4; i++) {
            int f = t + i * 256;              // 1024 float4 = 32x128 floats
            int r = f >> 5, c = f & 31;
            ((float4*)sW)[f] = ((const float4*)(W + (size_t)(kc + r) * HID))[c];
        }
        __syncthreads();
#pragma unroll
        for (int k0 = 0; k0 < 32; k0 += 4) {
            float4 w0 = *(const float4*)(sW + (k0 + 0) * HID + n0);
            float4 w1 = *(const float4*)(sW + (k0 + 1) * HID + n0);
            float4 w2 = *(const float4*)(sW + (k0 + 2) * HID + n0);
            float4 w3 = *(const float4*)(sW + (k0 + 3) * HID + n0);
#pragma unroll
            for (int i = 0; i < 8; i++) {
                float4 xv = *(const float4*)(sX + (m0 + i) * K + kc + k0);
                acc[i][0] += xv.x * w0.x + xv.y * w1.x + xv.z * w2.x + xv.w * w3.x;
                acc[i][1] += xv.x * w0.y + xv.y * w1.y + xv.z * w2.y + xv.w * w3.y;
                acc[i][2] += xv.x * w0.z + xv.y * w1.z + xv.z * w2.z + xv.w * w3.z;
                acc[i][3] += xv.x * w0.w + xv.y * w1.w + xv.z * w2.w + xv.w * w3.w;
            }
        }
    }
    const float b0 = sB[n0 + 0], b1 = sB[n0 + 1], b2 = sB[n0 + 2], b3 = sB[n0 + 3];
#pragma unroll
    for (int i = 0; i < 8; i++) {
        float4 h;
        h.x = fmaxf(acc[i][0] + b0, 0.f);
        h.y = fmaxf(acc[i][1] + b1, 0.f);
        h.z = fmaxf(acc[i][2] + b2, 0.f);
        h.w = fmaxf(acc[i][3] + b3, 0.f);
        *(float4*)(sH + (m0 + i) * HID + n0) = h;
    }
    __syncthreads();  // sH visible to readers
}

// ---------------------------------------------------------------------------
// layer2: gout[row_base+m][0:64] = sH[64][128] @ W[128][64] + bias
// 256 threads; microtile 4m x 4n.
// ---------------------------------------------------------------------------
__device__ __forceinline__ void layer2_tile(
    const float* __restrict__ W,      // global [128][64]
    const float* __restrict__ sH,     // shared [64][128]
    float* __restrict__ sW,           // shared buffer (used as [32][64])
    const float* __restrict__ sB,     // shared [64]
    float* __restrict__ gout, int row_base, int valid_rows, int t)
{
    const int nb = t & 15, mb = t >> 4;
    const int n0 = nb * 4, m0 = mb * 4;
    float acc[4][4];
#pragma unroll
    for (int i = 0; i < 4; i++)
#pragma unroll
        for (int j = 0; j < 4; j++) acc[i][j] = 0.f;

    for (int kc = 0; kc < 128; kc += 32) {
        __syncthreads();
#pragma unroll
        for (int i = 0; i < 2; i++) {
            int f = t + i * 256;              // 512 float4 = 32x64 floats
            int r = f >> 4, c = f & 15;
            ((float4*)sW)[f] = ((const float4*)(W + (size_t)(kc + r) * 64))[c];
        }
        __syncthreads();
#pragma unroll
        for (int k0 = 0; k0 < 32; k0 += 4) {
            float4 w0 = *(const float4*)(sW + (k0 + 0) * 64 + n0);
            float4 w1 = *(const float4*)(sW + (k0 + 1) * 64 + n0);
            float4 w2 = *(const float4*)(sW + (k0 + 2) * 64 + n0);
            float4 w3 = *(const float4*)(sW + (k0 + 3) * 64 + n0);
#pragma unroll
            for (int i = 0; i < 4; i++) {
                float4 xv = *(const float4*)(sH + (m0 + i) * HID + kc + k0);
                acc[i][0] += xv.x * w0.x + xv.y * w1.x + xv.z * w2.x + xv.w * w3.x;
                acc[i][1] += xv.x * w0.y + xv.y * w1.y + xv.z * w2.y + xv.w * w3.y;
                acc[i][2] += xv.x * w0.z + xv.y * w1.z + xv.z * w2.z + xv.w * w3.z;
                acc[i][3] += xv.x * w0.w + xv.y * w1.w + xv.z * w2.w + xv.w * w3.w;
            }
        }
    }
    const float b0 = sB[n0 + 0], b1 = sB[n0 + 1], b2 = sB[n0 + 2], b3 = sB[n0 + 3];
#pragma unroll
    for (int i = 0; i < 4; i++) {
        if (m0 + i < valid_rows) {
            float4 o;
            o.x = acc[i][0] + b0; o.y = acc[i][1] + b1;
            o.z = acc[i][2] + b2; o.w = acc[i][3] + b3;
            *(float4*)(gout + (size_t)(row_base + m0 + i) * 64 + n0) = o;
        }
    }
    __syncthreads();
}

// ---------------------------------------------------------------------------
// init scratch
// ---------------------------------------------------------------------------
__global__ void init_kernel() {
    int i = blockIdx.x * blockDim.x + threadIdx.x;
    if (i < NN) { g_segmax[i] = 0u; g_denom[i] = 0.f; }
    if (i < NN * EOUT) g_agg[i] = 0.f;
}

// ---------------------------------------------------------------------------
// edge kernel: 64 edges per CTA, 256 threads
// ---------------------------------------------------------------------------
__global__ void edge_kernel(
    const float* __restrict__ nf, const float* __restrict__ ef,
    const int* __restrict__ src, const int* __restrict__ dst,
    const float* __restrict__ We1, const float* __restrict__ be1,
    const float* __restrict__ We2, const float* __restrict__ be2,
    const float* __restrict__ Wa1, const float* __restrict__ ba1,
    const float* __restrict__ Wa2, const float* __restrict__ ba2,
    float* __restrict__ uhe)
{
    extern __shared__ float smem[];
    float* sX   = smem;                    // 64*160
    float* sW   = sX + 64 * KE;            // 32*128
    float* sH   = sW + 32 * HID;           // 64*128
    float* sBe1 = sH + 64 * HID;           // 128
    float* sBe2 = sBe1 + 128;              // 64
    float* sBa1 = sBe2 + 64;               // 128
    float* sWa2 = sBa1 + 128;              // 128
    int*   sIdx = (int*)(sWa2 + 128);      // 128 ints: src[0:64], dst[0:64]

    const int t  = threadIdx.x;
    const int e0 = blockIdx.x * 64;

    if (t < 128) { sBe1[t] = be1[t]; sBa1[t] = ba1[t]; sWa2[t] = Wa2[t]; }
    else if (t < 192) { sBe2[t - 128] = be2[t - 128]; }
    if (t < 64)        sIdx[t] = src[e0 + t];
    else if (t < 128)  sIdx[t] = dst[e0 + t - 64];
    __syncthreads();

    // gather: sX[m][0:64]=nf[src], [64:128]=nf[dst], [128:160]=ef  (2560 float4)
#pragma unroll
    for (int i = 0; i < 10; i++) {
        int f = t + i * 256;
        int m = f / 40, p = f % 40;
        float4 v;
        if (p < 16)       v = ((const float4*)(nf + (size_t)sIdx[m] * DIN))[p];
        else if (p < 32)  v = ((const float4*)(nf + (size_t)sIdx[64 + m] * DIN))[p - 16];
        else              v = ((const float4*)(ef + (size_t)(e0 + m) * EIN))[p - 32];
        *(float4*)(sX + m * KE + p * 4) = v;
    }
    __syncthreads();

    // edge-model MLP
    layer1_tile<KE>(We1, sX, sW, sH, sBe1, t);
    layer2_tile(We2, sH, sW, sBe2, uhe, e0, 64, t);

    // attention MLP hidden layer
    layer1_tile<KE>(Wa1, sX, sW, sH, sBa1, t);

    // logit: 4 threads / edge, each sums 32 of the 128 hidden values
    {
        const int m = t >> 2, l = t & 3;
        const float* hrow = sH + m * HID + l * 32;
        const float* wrow = sWa2 + l * 32;
        float s = 0.f;
#pragma unroll
        for (int j = 0; j < 32; j += 4) {
            float4 h = *(const float4*)(hrow + j);
            float4 w = *(const float4*)(wrow + j);
            s += h.x * w.x + h.y * w.y + h.z * w.z + h.w * w.w;
        }
        s += __shfl_xor_sync(0xffffffffu, s, 1);
        s += __shfl_xor_sync(0xffffffffu, s, 2);
        if (l == 0) {
            float logit = s + ba2[0];
            g_logit[e0 + m] = logit;
            atomicMax(&g_segmax[sIdx[64 + m]], fkey(logit));
        }
    }
}

// ---------------------------------------------------------------------------
// softmax denom: ex = exp(logit - segmax[dst]); denom[dst] += ex
// ---------------------------------------------------------------------------
__global__ void softmax_denom_kernel(const int* __restrict__ dst) {
    int e = blockIdx.x * 256 + threadIdx.x;
    if (e >= NE) return;
    int d = dst[e];
    float m = funkey(g_segmax[d]);
    float ex = expf(g_logit[e] - m);
    g_ex[e] = ex;
    atomicAdd(&g_denom[d], ex);
}

// ---------------------------------------------------------------------------
// aggregate: agg[dst] += uh_e * attn ; thread = (edge, 16B-quad)
// ---------------------------------------------------------------------------
__global__ void aggregate_kernel(const int* __restrict__ dst,
                                 const float* __restrict__ uhe) {
    int idx = blockIdx.x * 256 + threadIdx.x;   // NE*16 threads exactly
    int e = idx >> 4, q = idx & 15;
    int d = dst[e];
    float attn = g_ex[e] / fmaxf(g_denom[d], 1e-38f);
    float4 u = ((const float4*)(uhe + (size_t)e * EOUT))[q];
    float* a = g_agg + (size_t)d * EOUT + q * 4;
    atomicAdd(a + 0, u.x * attn);
    atomicAdd(a + 1, u.y * attn);
    atomicAdd(a + 2, u.z * attn);
    atomicAdd(a + 3, u.w * attn);
}

// ---------------------------------------------------------------------------
// node kernel: 64 nodes per CTA; in = concat(agg, nf) [128] -> 128 -> 64
// ---------------------------------------------------------------------------
__global__ void node_kernel(
    const float* __restrict__ nf,
    const float* __restrict__ Wn1, const float* __restrict__ bn1,
    const float* __restrict__ Wn2, const float* __restrict__ bn2,
    float* __restrict__ uhn)
{
    extern __shared__ float smem[];
    float* sX  = smem;                 // 64*128
    float* sW  = sX + 64 * 128;        // 32*128
    float* sH  = sW + 32 * HID;        // 64*128
    float* sB1 = sH + 64 * HID;        // 128
    float* sB2 = sB1 + 128;            // 64

    const int t   = threadIdx.x;
    const int n0b = blockIdx.x * 64;

    if (t < 128) sB1[t] = bn1[t];
    else if (t < 192) sB2[t - 128] = bn2[t - 128];

#pragma unroll
    for (int i = 0; i < 8; i++) {
        int f = t + i * 256;           // 2048 float4 = 64x128 floats
        int m = f >> 5, p = f & 31;
        int node = n0b + m;
        int nc = node < NN ? node : NN - 1;
        float4 v;
        if (p < 16) v = ((const float4*)(g_agg + (size_t)nc * EOUT))[p];
        else        v = ((const float4*)(nf + (size_t)nc * DIN))[p - 16];
        *(float4*)(sX + m * 128 + p * 4) = v;
    }
    __syncthreads();

    layer1_tile<128>(Wn1, sX, sW, sH, sB1, t);
    layer2_tile(Wn2, sH, sW, sB2, uhn, n0b, NN - n0b, t);
}

// ---------------------------------------------------------------------------
extern "C" void kernel_launch(void* const* d_in, const int* in_sizes, int n_in,
                              void* d_out, int out_size) {
    const float* nf  = (const float*)d_in[0];
    const float* ef  = (const float*)d_in[1];
    const int*   src = (const int*)d_in[2];
    const int*   dst = (const int*)d_in[3];
    const float* We1 = (const float*)d_in[4];
    const float* be1 = (const float*)d_in[5];
    const float* We2 = (const float*)d_in[6];
    const float* be2 = (const float*)d_in[7];
    const float* Wa1 = (const float*)d_in[8];
    const float* ba1 = (const float*)d_in[9];
    const float* Wa2 = (const float*)d_in[10];
    const float* ba2 = (const float*)d_in[11];
    const float* Wn1 = (const float*)d_in[12];
    const float* bn1 = (const float*)d_in[13];
    const float* Wn2 = (const float*)d_in[14];
    const float* bn2 = (const float*)d_in[15];

    float* out = (float*)d_out;
    float* uhn = out;                              // [NN, DOUT]
    float* uhe = out + (size_t)NN * DOUT;          // [NE, EOUT]

    const int SMEM_E = (64 * KE + 32 * HID + 64 * HID + 128 + 64 + 128 + 128 + 128) * 4;
    const int SMEM_N = (64 * 128 + 32 * HID + 64 * HID + 128 + 64) * 4;

    cudaFuncSetAttribute(edge_kernel, cudaFuncAttributeMaxDynamicSharedMemorySize, SMEM_E);
    cudaFuncSetAttribute(node_kernel, cudaFuncAttributeMaxDynamicSharedMemorySize, SMEM_N);

    init_kernel<<<(NN * EOUT + 255) / 256, 256>>>();
    edge_kernel<<<NE / 64, 256, SMEM_E>>>(nf, ef, src, dst,
                                          We1, be1, We2, be2,
                                          Wa1, ba1, Wa2, ba2, uhe);
    softmax_denom_kernel<<<(NE + 255) / 256, 256>>>(dst);
    aggregate_kernel<<<(NE * 16) / 256, 256>>>(dst, uhe);
    node_kernel<<<(NN + 63) / 64, 256, SMEM_N>>>(nf, Wn1, bn1, Wn2, bn2, uhn);
}

// round 5
// speedup vs baseline: 1.5834x; 1.5834x over previous
#include <cuda_runtime.h>
#include <cuda_fp16.h>
#include <cstdint>

#define NN   50000
#define NE   800000
#define DIN  64
#define EIN  32
#define KE   160
#define K1P  192       // K padded for layer1
#define SA1  200       // SMEM stride (elements) for A / W1 images (192+8)
#define SH3  136       // SMEM stride for H / We2 images (128+8)
#define HID  128
#define EOUT 64
#define DOUT 64

// ---------------- scratch ----------------
__device__ unsigned g_segmax[NN];
__device__ float    g_denom[NN];
__device__ float    g_agg[(size_t)NN * EOUT];
__device__ float    g_logit[NE];
__device__ float    g_ex[NE];

// weight images: W^T row-major [n][k] with padded stride, fp16 hi/lo
__device__ __align__(16) __half g_Wa1h[128 * SA1], g_Wa1l[128 * SA1];
__device__ __align__(16) __half g_We1h[128 * SA1], g_We1l[128 * SA1];
__device__ __align__(16) __half g_We2h[64 * SH3],  g_We2l[64 * SH3];

__device__ __forceinline__ unsigned fkey(float f) {
    int i = __float_as_int(f);
    return (i >= 0) ? (unsigned(i) | 0x80000000u) : ~unsigned(i);
}
__device__ __forceinline__ float funkey(unsigned k) {
    int i = (k & 0x80000000u) ? int(k & 0x7fffffffu) : ~int(k);
    return __int_as_float(i);
}
__device__ __forceinline__ uint32_t smem_u32(const void* p) {
    uint32_t a;
    asm("{ .reg .u64 t; cvta.to.shared.u64 t, %1; cvt.u32.u64 %0, t; }" : "=r"(a) : "l"(p));
    return a;
}
__device__ __forceinline__ void split2(float x, float y, uint32_t& hi, uint32_t& lo) {
    __half hx = __float2half_rn(x), hy = __float2half_rn(y);
    __half lx = __float2half_rn(x - __half2float(hx));
    __half ly = __float2half_rn(y - __half2float(hy));
    __half2 h = __halves2half2(hx, hy), l = __halves2half2(lx, ly);
    hi = *reinterpret_cast<uint32_t*>(&h);
    lo = *reinterpret_cast<uint32_t*>(&l);
}

#define LDSM4(r0, r1, r2, r3, a) \
    asm volatile("ldmatrix.sync.aligned.m8n8.x4.shared.b16 {%0,%1,%2,%3}, [%4];" \
        : "=r"(r0), "=r"(r1), "=r"(r2), "=r"(r3) : "r"(a))
#define LDSM2(r0, r1, a) \
    asm volatile("ldmatrix.sync.aligned.m8n8.x2.shared.b16 {%0,%1}, [%2];" \
        : "=r"(r0), "=r"(r1) : "r"(a))
#define MMA(cc, a0, a1, a2, a3, b0, b1) \
    asm volatile("mma.sync.aligned.m16n8k16.row.col.f32.f16.f16.f32 " \
        "{%0,%1,%2,%3}, {%4,%5,%6,%7}, {%8,%9}, {%0,%1,%2,%3};" \
        : "+f"((cc)[0]), "+f"((cc)[1]), "+f"((cc)[2]), "+f"((cc)[3]) \
        : "r"(a0), "r"(a1), "r"(a2), "r"(a3), "r"(b0), "r"(b1))

// 3-product split-fp16 warp GEMM: C[2][NS][4] += A[32 x 16K] * B^T
// aH/aL/bH/bL are lane-adjusted byte addresses at (m_base,0)/(n_base,0).
template <int KS, int NS, int SAe, int SBe>
__device__ __forceinline__ void gemm3(float C[2][NS][4],
                                      uint32_t aH, uint32_t aL,
                                      uint32_t bH, uint32_t bL) {
    const uint32_t aMs = 16u * SAe * 2u;
    const uint32_t bNs = 8u * SBe * 2u;
    // pass 1: Bh with Ah and Al
#pragma unroll 1
    for (int k = 0; k < KS; k++) {
        uint32_t ka = (uint32_t)k * 32u;
        uint32_t h0, h1, h2, h3, h4, h5, h6, h7, l0, l1, l2, l3, l4, l5, l6, l7;
        LDSM4(h0, h1, h2, h3, aH + ka);
        LDSM4(h4, h5, h6, h7, aH + aMs + ka);
        LDSM4(l0, l1, l2, l3, aL + ka);
        LDSM4(l4, l5, l6, l7, aL + aMs + ka);
#pragma unroll
        for (int n = 0; n < NS; n++) {
            uint32_t b0, b1;
            LDSM2(b0, b1, bH + n * bNs + ka);
            MMA(C[0][n], h0, h1, h2, h3, b0, b1);
            MMA(C[1][n], h4, h5, h6, h7, b0, b1);
            MMA(C[0][n], l0, l1, l2, l3, b0, b1);
            MMA(C[1][n], l4, l5, l6, l7, b0, b1);
        }
    }
    // pass 2: Bl with Ah
#pragma unroll 1
    for (int k = 0; k < KS; k++) {
        uint32_t ka = (uint32_t)k * 32u;
        uint32_t h0, h1, h2, h3, h4, h5, h6, h7;
        LDSM4(h0, h1, h2, h3, aH + ka);
        LDSM4(h4, h5, h6, h7, aH + aMs + ka);
#pragma unroll
        for (int n = 0; n < NS; n++) {
            uint32_t b0, b1;
            LDSM2(b0, b1, bL + n * bNs + ka);
            MMA(C[0][n], h0, h1, h2, h3, b0, b1);
            MMA(C[1][n], h4, h5, h6, h7, b0, b1);
        }
    }
}

// ---------------------------------------------------------------------------
// prep: build W^T fp16 hi/lo images with padded strides
// ---------------------------------------------------------------------------
__global__ void prep_weights(const float* __restrict__ Wa1, const float* __restrict__ We1,
                             const float* __restrict__ We2) {
    int i = blockIdx.x * 256 + threadIdx.x;
    float v;
    __half *ph, *pl;
    int idx;
    if (i < 128 * SA1) {
        int n = i / SA1, c = i % SA1;
        v = (c < KE) ? Wa1[c * HID + n] : 0.f;
        ph = g_Wa1h; pl = g_Wa1l; idx = i;
    } else if (i < 2 * 128 * SA1) {
        int j = i - 128 * SA1;
        int n = j / SA1, c = j % SA1;
        v = (c < KE) ? We1[c * HID + n] : 0.f;
        ph = g_We1h; pl = g_We1l; idx = j;
    } else if (i < 2 * 128 * SA1 + 64 * SH3) {
        int j = i - 2 * 128 * SA1;
        int n = j / SH3, c = j % SH3;
        v = (c < HID) ? We2[c * EOUT + n] : 0.f;
        ph = g_We2h; pl = g_We2l; idx = j;
    } else return;
    __half h = __float2half_rn(v);
    __half l = __float2half_rn(v - __half2float(h));
    ph[idx] = h;
    pl[idx] = l;
}

__global__ void init_kernel() {
    int i = blockIdx.x * blockDim.x + threadIdx.x;
    if (i < NN) { g_segmax[i] = 0u; g_denom[i] = 0.f; }
    if (i < NN * EOUT) g_agg[i] = 0.f;
}

// ---------------------------------------------------------------------------
// edge kernel: 128 edges/CTA, 256 threads (8 warps = 4m x 2n)
// ---------------------------------------------------------------------------
#define OFF_IDX  0u           // 256 int
#define OFF_BE1  1024u        // 128 f
#define OFF_BA1  1536u
#define OFF_WA2  2048u
#define OFF_BE2  2560u        // 64 f
#define OFF_LOG  2816u        // 256 f
#define OFF_AH   4096u        // 128*200*2 = 51200
#define OFF_AL   (OFF_AH + 51200u)
#define OFF_BH   (OFF_AL + 51200u)
#define OFF_BL   (OFF_BH + 51200u)
#define SMEM_E   (OFF_BL + 51200u)   // 208896

__global__ void __launch_bounds__(256) edge_hmma_kernel(
    const float* __restrict__ nf, const float* __restrict__ ef,
    const int* __restrict__ src, const int* __restrict__ dst,
    const float* __restrict__ be1, const float* __restrict__ ba1,
    const float* __restrict__ Wa2, const float* __restrict__ ba2,
    const float* __restrict__ be2, float* __restrict__ uhe)
{
    extern __shared__ __align__(1024) unsigned char smem[];
    const uint32_t sb = smem_u32(smem);
    const int t = threadIdx.x, w = t >> 5, lane = t & 31;
    const int e0 = blockIdx.x * 128;
    const int wm = w >> 1, wn = w & 1;
    const int m_base = wm * 32;

    int*   sIdx = (int*)(smem + OFF_IDX);
    float* sBe1 = (float*)(smem + OFF_BE1);
    float* sBa1 = (float*)(smem + OFF_BA1);
    float* sWa2 = (float*)(smem + OFF_WA2);
    float* sBe2 = (float*)(smem + OFF_BE2);
    float* sLog = (float*)(smem + OFF_LOG);

    if (t < 128) { sBe1[t] = be1[t]; sBa1[t] = ba1[t]; sWa2[t] = Wa2[t]; sIdx[t] = src[e0 + t]; }
    else { sIdx[t] = dst[e0 + t - 128]; if (t < 192) sBe2[t - 128] = be2[t - 128]; }
    __syncthreads();

    // zero A pad cols 160..199 (both images); 128 rows x 20 col-pairs
    for (int idx = t; idx < 2560; idx += 256) {
        int r = idx / 20, c = 160 + (idx % 20) * 2;
        uint32_t off = (uint32_t)(r * SA1 + c) * 2u;
        *(uint32_t*)(smem + OFF_AH + off) = 0u;
        *(uint32_t*)(smem + OFF_AL + off) = 0u;
    }
    // gather e_in -> A hi/lo (128 x 40 float4)
#pragma unroll
    for (int i = 0; i < 20; i++) {
        int f = t + i * 256;
        int m = f / 40, p = f % 40;
        float4 v;
        if (p < 16)       v = ((const float4*)(nf + (size_t)sIdx[m] * DIN))[p];
        else if (p < 32)  v = ((const float4*)(nf + (size_t)sIdx[128 + m] * DIN))[p - 16];
        else              v = ((const float4*)(ef + (size_t)(e0 + m) * EIN))[p - 32];
        uint32_t h01, l01, h23, l23;
        split2(v.x, v.y, h01, l01);
        split2(v.z, v.w, h23, l23);
        uint32_t off = (uint32_t)(m * SA1 + p * 4) * 2u;
        *(uint2*)(smem + OFF_AH + off) = make_uint2(h01, h23);
        *(uint2*)(smem + OFF_AL + off) = make_uint2(l01, l23);
    }
    // copy Wa1 images (3200 uint4 each)
    for (int idx = t; idx < 6400; idx += 256) {
        if (idx < 3200) ((uint4*)(smem + OFF_BH))[idx] = ((const uint4*)g_Wa1h)[idx];
        else            ((uint4*)(smem + OFF_BL))[idx - 3200] = ((const uint4*)g_Wa1l)[idx - 3200];
    }
    __syncthreads();

    // lane-adjusted base addresses
    const uint32_t laneA1 = (uint32_t)(((lane & 15) * SA1 + (lane >> 4) * 8) * 2);
    const uint32_t laneB1 = (uint32_t)(((lane & 7) * SA1 + ((lane >> 3) & 1) * 8) * 2);
    const uint32_t laneA3 = (uint32_t)(((lane & 15) * SH3 + (lane >> 4) * 8) * 2);
    const uint32_t laneB3 = (uint32_t)(((lane & 7) * SH3 + ((lane >> 3) & 1) * 8) * 2);
    const uint32_t aHb = sb + OFF_AH + (uint32_t)(m_base * SA1) * 2u + laneA1;
    const uint32_t aLb = sb + OFF_AL + (uint32_t)(m_base * SA1) * 2u + laneA1;

    // ---------------- phase 1: attention hidden + logits ----------------
    {
        const int n_base = wn * 64;
        float C[2][8][4];
#pragma unroll
        for (int ms = 0; ms < 2; ms++)
#pragma unroll
            for (int n = 0; n < 8; n++)
#pragma unroll
                for (int j = 0; j < 4; j++) C[ms][n][j] = 0.f;
        uint32_t bHb = sb + OFF_BH + (uint32_t)(n_base * SA1) * 2u + laneB1;
        uint32_t bLb = sb + OFF_BL + (uint32_t)(n_base * SA1) * 2u + laneB1;
        gemm3<12, 8, SA1, SA1>(C, aHb, aLb, bHb, bLb);
        // logit partials
#pragma unroll
        for (int ms = 0; ms < 2; ms++) {
            float p0 = 0.f, p1 = 0.f;
#pragma unroll
            for (int n = 0; n < 8; n++) {
                int col = n_base + n * 8 + (lane & 3) * 2;
                float w0 = sWa2[col], w1 = sWa2[col + 1];
                float b0 = sBa1[col], b1 = sBa1[col + 1];
                p0 += fmaxf(C[ms][n][0] + b0, 0.f) * w0 + fmaxf(C[ms][n][1] + b1, 0.f) * w1;
                p1 += fmaxf(C[ms][n][2] + b0, 0.f) * w0 + fmaxf(C[ms][n][3] + b1, 0.f) * w1;
            }
            p0 += __shfl_xor_sync(0xffffffffu, p0, 1);
            p0 += __shfl_xor_sync(0xffffffffu, p0, 2);
            p1 += __shfl_xor_sync(0xffffffffu, p1, 1);
            p1 += __shfl_xor_sync(0xffffffffu, p1, 2);
            if ((lane & 3) == 0) {
                int r = m_base + ms * 16 + (lane >> 2);
                sLog[wn * 128 + r] = p0;
                sLog[wn * 128 + r + 8] = p1;
            }
        }
    }
    __syncthreads();   // sLog done; all warps done reading sB (Wa1)

    if (t < 128) {
        float lg = sLog[t] + sLog[128 + t] + ba2[0];
        g_logit[e0 + t] = lg;
        atomicMax(&g_segmax[sIdx[128 + t]], fkey(lg));
    }
    // copy We1 images
    for (int idx = t; idx < 6400; idx += 256) {
        if (idx < 3200) ((uint4*)(smem + OFF_BH))[idx] = ((const uint4*)g_We1h)[idx];
        else            ((uint4*)(smem + OFF_BL))[idx - 3200] = ((const uint4*)g_We1l)[idx - 3200];
    }
    __syncthreads();

    // ---------------- phase 2: edge-MLP hidden ----------------
    {
        const int n_base = wn * 64;
        float C[2][8][4];
#pragma unroll
        for (int ms = 0; ms < 2; ms++)
#pragma unroll
            for (int n = 0; n < 8; n++)
#pragma unroll
                for (int j = 0; j < 4; j++) C[ms][n][j] = 0.f;
        uint32_t bHb = sb + OFF_BH + (uint32_t)(n_base * SA1) * 2u + laneB1;
        uint32_t bLb = sb + OFF_BL + (uint32_t)(n_base * SA1) * 2u + laneB1;
        gemm3<12, 8, SA1, SA1>(C, aHb, aLb, bHb, bLb);
        __syncthreads();   // everyone finished reading sA (e_in) and sB (We1)
        // H = relu(C + be1) -> fp16 hi/lo into A region (stride 136)
#pragma unroll
        for (int ms = 0; ms < 2; ms++) {
            int r0 = m_base + ms * 16 + (lane >> 2), r1 = r0 + 8;
#pragma unroll
            for (int n = 0; n < 8; n++) {
                int col = n_base + n * 8 + (lane & 3) * 2;
                float b0 = sBe1[col], b1 = sBe1[col + 1];
                float x0 = fmaxf(C[ms][n][0] + b0, 0.f), x1 = fmaxf(C[ms][n][1] + b1, 0.f);
                float x2 = fmaxf(C[ms][n][2] + b0, 0.f), x3 = fmaxf(C[ms][n][3] + b1, 0.f);
                uint32_t h, l;
                split2(x0, x1, h, l);
                uint32_t off0 = (uint32_t)(r0 * SH3 + col) * 2u;
                *(uint32_t*)(smem + OFF_AH + off0) = h;
                *(uint32_t*)(smem + OFF_AL + off0) = l;
                split2(x2, x3, h, l);
                uint32_t off1 = (uint32_t)(r1 * SH3 + col) * 2u;
                *(uint32_t*)(smem + OFF_AH + off1) = h;
                *(uint32_t*)(smem + OFF_AL + off1) = l;
            }
        }
    }
    // copy We2 images (1088 uint4 each)
    for (int idx = t; idx < 2176; idx += 256) {
        if (idx < 1088) ((uint4*)(smem + OFF_BH))[idx] = ((const uint4*)g_We2h)[idx];
        else            ((uint4*)(smem + OFF_BL))[idx - 1088] = ((const uint4*)g_We2l)[idx - 1088];
    }
    __syncthreads();

    // ---------------- phase 3: uh_e = H @ We2 + be2 ----------------
    {
        const int n_base = wn * 32;
        float C[2][4][4];
#pragma unroll
        for (int ms = 0; ms < 2; ms++)
#pragma unroll
            for (int n = 0; n < 4; n++)
#pragma unroll
                for (int j = 0; j < 4; j++) C[ms][n][j] = 0.f;
        uint32_t aH3 = sb + OFF_AH + (uint32_t)(m_base * SH3) * 2u + laneA3;
        uint32_t aL3 = sb + OFF_AL + (uint32_t)(m_base * SH3) * 2u + laneA3;
        uint32_t bH3 = sb + OFF_BH + (uint32_t)(n_base * SH3) * 2u + laneB3;
        uint32_t bL3 = sb + OFF_BL + (uint32_t)(n_base * SH3) * 2u + laneB3;
        gemm3<8, 4, SH3, SH3>(C, aH3, aL3, bH3, bL3);
#pragma unroll
        for (int ms = 0; ms < 2; ms++) {
            int r0 = m_base + ms * 16 + (lane >> 2), r1 = r0 + 8;
#pragma unroll
            for (int n = 0; n < 4; n++) {
                int col = n_base + n * 8 + (lane & 3) * 2;
                float b0 = sBe2[col], b1 = sBe2[col + 1];
                float2 o0 = make_float2(C[ms][n][0] + b0, C[ms][n][1] + b1);
                float2 o1 = make_float2(C[ms][n][2] + b0, C[ms][n][3] + b1);
                *(float2*)(uhe + (size_t)(e0 + r0) * 64 + col) = o0;
                *(float2*)(uhe + (size_t)(e0 + r1) * 64 + col) = o1;
            }
        }
    }
}

// ---------------------------------------------------------------------------
__global__ void softmax_denom_kernel(const int* __restrict__ dst) {
    int e = blockIdx.x * 256 + threadIdx.x;
    if (e >= NE) return;
    int d = dst[e];
    float m = funkey(g_segmax[d]);
    float ex = expf(g_logit[e] - m);
    g_ex[e] = ex;
    atomicAdd(&g_denom[d], ex);
}

__global__ void aggregate_kernel(const int* __restrict__ dst,
                                 const float* __restrict__ uhe) {
    int idx = blockIdx.x * 256 + threadIdx.x;
    int e = idx >> 4, q = idx & 15;
    int d = dst[e];
    float attn = g_ex[e] / fmaxf(g_denom[d], 1e-38f);
    float4 u = ((const float4*)(uhe + (size_t)e * EOUT))[q];
    float* a = g_agg + (size_t)d * EOUT + q * 4;
    atomicAdd(a + 0, u.x * attn);
    atomicAdd(a + 1, u.y * attn);
    atomicAdd(a + 2, u.z * attn);
    atomicAdd(a + 3, u.w * attn);
}

// ---------------------------------------------------------------------------
// node FFMA path (small: ~1.2 G-MAC)
// ---------------------------------------------------------------------------
template <int K>
__device__ __forceinline__ void layer1_tile(
    const float* __restrict__ W, const float* __restrict__ sX,
    float* __restrict__ sW, float* __restrict__ sH,
    const float* __restrict__ sB, int t)
{
    const int nb = t & 31, mb = t >> 5;
    const int n0 = nb * 4, m0 = mb * 8;
    float acc[8][4];
#pragma unroll
    for (int i = 0; i < 8; i++)
#pragma unroll
        for (int j = 0; j < 4; j++) acc[i][j] = 0.f;
    for (int kc = 0; kc < K; kc += 32) {
        __syncthreads();
#pragma unroll
        for (int i = 0; i < 4; i++) {
            int f = t + i * 256, r = f >> 5, c = f & 31;
            ((float4*)sW)[f] = ((const float4*)(W + (size_t)(kc + r) * HID))[c];
        }
        __syncthreads();
#pragma unroll
        for (int k0 = 0; k0 < 32; k0 += 4) {
            float4 w0 = *(const float4*)(sW + (k0 + 0) * HID + n0);
            float4 w1 = *(const float4*)(sW + (k0 + 1) * HID + n0);
            float4 w2 = *(const float4*)(sW + (k0 + 2) * HID + n0);
            float4 w3 = *(const float4*)(sW + (k0 + 3) * HID + n0);
#pragma unroll
            for (int i = 0; i < 8; i++) {
                float4 xv = *(const float4*)(sX + (m0 + i) * K + kc + k0);
                acc[i][0] += xv.x * w0.x + xv.y * w1.x + xv.z * w2.x + xv.w * w3.x;
                acc[i][1] += xv.x * w0.y + xv.y * w1.y + xv.z * w2.y + xv.w * w3.y;
                acc[i][2] += xv.x * w0.z + xv.y * w1.z + xv.z * w2.z + xv.w * w3.z;
                acc[i][3] += xv.x * w0.w + xv.y * w1.w + xv.z * w2.w + xv.w * w3.w;
            }
        }
    }
    const float b0 = sB[n0], b1 = sB[n0+1], b2 = sB[n0+2], b3 = sB[n0+3];
#pragma unroll
    for (int i = 0; i < 8; i++) {
        float4 h;
        h.x = fmaxf(acc[i][0] + b0, 0.f); h.y = fmaxf(acc[i][1] + b1, 0.f);
        h.z = fmaxf(acc[i][2] + b2, 0.f); h.w = fmaxf(acc[i][3] + b3, 0.f);
        *(float4*)(sH + (m0 + i) * HID + n0) = h;
    }
    __syncthreads();
}

__device__ __forceinline__ void layer2_tile(
    const float* __restrict__ W, const float* __restrict__ sH,
    float* __restrict__ sW, const float* __restrict__ sB,
    float* __restrict__ gout, int row_base, int valid_rows, int t)
{
    const int nb = t & 15, mb = t >> 4;
    const int n0 = nb * 4, m0 = mb * 4;
    float acc[4][4];
#pragma unroll
    for (int i = 0; i < 4; i++)
#pragma unroll
        for (int j = 0; j < 4; j++) acc[i][j] = 0.f;
    for (int kc = 0; kc < 128; kc += 32) {
        __syncthreads();
#pragma unroll
        for (int i = 0; i < 2; i++) {
            int f = t + i * 256, r = f >> 4, c = f & 15;
            ((float4*)sW)[f] = ((const float4*)(W + (size_t)(kc + r) * 64))[c];
        }
        __syncthreads();
#pragma unroll
        for (int k0 = 0; k0 < 32; k0 += 4) {
            float4 w0 = *(const float4*)(sW + (k0 + 0) * 64 + n0);
            float4 w1 = *(const float4*)(sW + (k0 + 1) * 64 + n0);
            float4 w2 = *(const float4*)(sW + (k0 + 2) * 64 + n0);
            float4 w3 = *(const float4*)(sW + (k0 + 3) * 64 + n0);
#pragma unroll
            for (int i = 0; i < 4; i++) {
                float4 xv = *(const float4*)(sH + (m0 + i) * HID + kc + k0);
                acc[i][0] += xv.x * w0.x + xv.y * w1.x + xv.z * w2.x + xv.w * w3.x;
                acc[i][1] += xv.x * w0.y + xv.y * w1.y + xv.z * w2.y + xv.w * w3.y;
                acc[i][2] += xv.x * w0.z + xv.y * w1.z + xv.z * w2.z + xv.w * w3.z;
                acc[i][3] += xv.x * w0.w + xv.y * w1.w + xv.z * w2.w + xv.w * w3.w;
            }
        }
    }
    const float b0 = sB[n0], b1 = sB[n0+1], b2 = sB[n0+2], b3 = sB[n0+3];
#pragma unroll
    for (int i = 0; i < 4; i++) {
        if (m0 + i < valid_rows) {
            float4 o;
            o.x = acc[i][0] + b0; o.y = acc[i][1] + b1;
            o.z = acc[i][2] + b2; o.w = acc[i][3] + b3;
            *(float4*)(gout + (size_t)(row_base + m0 + i) * 64 + n0) = o;
        }
    }
    __syncthreads();
}

__global__ void node_kernel(
    const float* __restrict__ nf,
    const float* __restrict__ Wn1, const float* __restrict__ bn1,
    const float* __restrict__ Wn2, const float* __restrict__ bn2,
    float* __restrict__ uhn)
{
    extern __shared__ float fsmem[];
    float* sX  = fsmem;
    float* sW  = sX + 64 * 128;
    float* sH  = sW + 32 * HID;
    float* sB1 = sH + 64 * HID;
    float* sB2 = sB1 + 128;
    const int t = threadIdx.x;
    const int n0b = blockIdx.x * 64;
    if (t < 128) sB1[t] = bn1[t];
    else if (t < 192) sB2[t - 128] = bn2[t - 128];
#pragma unroll
    for (int i = 0; i < 8; i++) {
        int f = t + i * 256, m = f >> 5, p = f & 31;
        int node = n0b + m;
        int nc = node < NN ? node : NN - 1;
        float4 v;
        if (p < 16) v = ((const float4*)(g_agg + (size_t)nc * EOUT))[p];
        else        v = ((const float4*)(nf + (size_t)nc * DIN))[p - 16];
        *(float4*)(sX + m * 128 + p * 4) = v;
    }
    __syncthreads();
    layer1_tile<128>(Wn1, sX, sW, sH, sB1, t);
    layer2_tile(Wn2, sH, sW, sB2, uhn, n0b, NN - n0b, t);
}

// ---------------------------------------------------------------------------
extern "C" void kernel_launch(void* const* d_in, const int* in_sizes, int n_in,
                              void* d_out, int out_size) {
    const float* nf  = (const float*)d_in[0];
    const float* ef  = (const float*)d_in[1];
    const int*   src = (const int*)d_in[2];
    const int*   dst = (const int*)d_in[3];
    const float* We1 = (const float*)d_in[4];
    const float* be1 = (const float*)d_in[5];
    const float* We2 = (const float*)d_in[6];
    const float* be2 = (const float*)d_in[7];
    const float* Wa1 = (const float*)d_in[8];
    const float* ba1 = (const float*)d_in[9];
    const float* Wa2 = (const float*)d_in[10];
    const float* ba2 = (const float*)d_in[11];
    const float* Wn1 = (const float*)d_in[12];
    const float* bn1 = (const float*)d_in[13];
    const float* Wn2 = (const float*)d_in[14];
    const float* bn2 = (const float*)d_in[15];

    float* out = (float*)d_out;
    float* uhn = out;                              // [NN, DOUT]
    float* uhe = out + (size_t)NN * DOUT;          // [NE, EOUT]

    const int SMEM_N = (64 * 128 + 32 * HID + 64 * HID + 128 + 64) * 4;
    cudaFuncSetAttribute(edge_hmma_kernel, cudaFuncAttributeMaxDynamicSharedMemorySize, SMEM_E);
    cudaFuncSetAttribute(node_kernel, cudaFuncAttributeMaxDynamicSharedMemorySize, SMEM_N);

    const int prep_elems = 2 * 128 * SA1 + 64 * SH3;   // 59904
    prep_weights<<<(prep_elems + 255) / 256, 256>>>(Wa1, We1, We2);
    init_kernel<<<(NN * EOUT + 255) / 256, 256>>>();
    edge_hmma_kernel<<<NE / 128, 256, SMEM_E>>>(nf, ef, src, dst,
                                                be1, ba1, Wa2, ba2, be2, uhe);
    softmax_denom_kernel<<<(NE + 255) / 256, 256>>>(dst);
    aggregate_kernel<<<(NE * 16) / 256, 256>>>(dst, uhe);
    node_kernel<<<(NN + 63) / 64, 256, SMEM_N>>>(nf, Wn1, bn1, Wn2, bn2, uhn);
}

// round 7
// speedup vs baseline: 1.8347x; 1.1587x over previous
#include <cuda_runtime.h>
#include <cuda_fp16.h>
#include <cstdint>

#define NN   50000
#define NE   800000
#define DIN  64
#define EIN  32
#define KE   160
#define SA1  200       // SMEM stride (elements) for A / W1 images (192+8)
#define SH3  136       // SMEM stride for H / We2 images (128+8)
#define HID  128
#define EOUT 64
#define DOUT 64

// ---------------- scratch ----------------
__device__ unsigned g_segmax[NN];
__device__ float    g_denom[NN];
__device__ float    g_agg[(size_t)NN * EOUT];
__device__ float    g_logit[NE];
__device__ float    g_ex[NE];

// weight images: W^T row-major [n][k] with padded stride, fp16 (hi only)
__device__ __align__(16) __half g_Wa1h[128 * SA1];
__device__ __align__(16) __half g_We1h[128 * SA1];
__device__ __align__(16) __half g_We2h[64 * SH3];

__device__ __forceinline__ unsigned fkey(float f) {
    int i = __float_as_int(f);
    return (i >= 0) ? (unsigned(i) | 0x80000000u) : ~unsigned(i);
}
__device__ __forceinline__ float funkey(unsigned k) {
    int i = (k & 0x80000000u) ? int(k & 0x7fffffffu) : ~int(k);
    return __int_as_float(i);
}
__device__ __forceinline__ uint32_t smem_u32(const void* p) {
    uint32_t a;
    asm("{ .reg .u64 t; cvta.to.shared.u64 t, %1; cvt.u32.u64 %0, t; }" : "=r"(a) : "l"(p));
    return a;
}
__device__ __forceinline__ void split2(float x, float y, uint32_t& hi, uint32_t& lo) {
    __half hx = __float2half_rn(x), hy = __float2half_rn(y);
    __half lx = __float2half_rn(x - __half2float(hx));
    __half ly = __float2half_rn(y - __half2float(hy));
    __half2 h = __halves2half2(hx, hy), l = __halves2half2(lx, ly);
    hi = *reinterpret_cast<uint32_t*>(&h);
    lo = *reinterpret_cast<uint32_t*>(&l);
}

#define LDSM4(r0, r1, r2, r3, a) \
    asm volatile("ldmatrix.sync.aligned.m8n8.x4.shared.b16 {%0,%1,%2,%3}, [%4];" \
        : "=r"(r0), "=r"(r1), "=r"(r2), "=r"(r3) : "r"(a))
#define MMA(cc, a0, a1, a2, a3, b0, b1) \
    asm volatile("mma.sync.aligned.m16n8k16.row.col.f32.f16.f16.f32 " \
        "{%0,%1,%2,%3}, {%4,%5,%6,%7}, {%8,%9}, {%0,%1,%2,%3};" \
        : "+f"((cc)[0]), "+f"((cc)[1]), "+f"((cc)[2]), "+f"((cc)[3]) \
        : "r"(a0), "r"(a1), "r"(a2), "r"(a3), "r"(b0), "r"(b1))

// 2-product split-fp16 warp GEMM: C += (Ah + Al) * Bh^T
// aH/aL lane-adjusted A addresses; bH lane-adjusted for n-PAIR ldmatrix.x4:
// lanes 0-7:(n,k0) 8-15:(n,k8) 16-23:(n+8,k0) 24-31:(n+8,k8)
template <int KS, int NS, int SAe, int SBe>
__device__ __forceinline__ void gemm2(float C[2][NS][4],
                                      uint32_t aH, uint32_t aL, uint32_t bH) {
    const uint32_t aMs = 16u * SAe * 2u;
    const uint32_t bPs = 16u * SBe * 2u;   // stride per n-pair (16 rows)
#pragma unroll 1
    for (int k = 0; k < KS; k++) {
        uint32_t ka = (uint32_t)k * 32u;
        uint32_t h0, h1, h2, h3, h4, h5, h6, h7, l0, l1, l2, l3, l4, l5, l6, l7;
        LDSM4(h0, h1, h2, h3, aH + ka);
        LDSM4(h4, h5, h6, h7, aH + aMs + ka);
        LDSM4(l0, l1, l2, l3, aL + ka);
        LDSM4(l4, l5, l6, l7, aL + aMs + ka);
#pragma unroll
        for (int p = 0; p < NS / 2; p++) {
            uint32_t b0, b1, b2, b3;
            LDSM4(b0, b1, b2, b3, bH + (uint32_t)p * bPs + ka);
            MMA(C[0][2*p],   h0, h1, h2, h3, b0, b1);
            MMA(C[1][2*p],   h4, h5, h6, h7, b0, b1);
            MMA(C[0][2*p+1], h0, h1, h2, h3, b2, b3);
            MMA(C[1][2*p+1], h4, h5, h6, h7, b2, b3);
            MMA(C[0][2*p],   l0, l1, l2, l3, b0, b1);
            MMA(C[1][2*p],   l4, l5, l6, l7, b0, b1);
            MMA(C[0][2*p+1], l0, l1, l2, l3, b2, b3);
            MMA(C[1][2*p+1], l4, l5, l6, l7, b2, b3);
        }
    }
}

// ---------------------------------------------------------------------------
// prep: build W^T fp16 images with padded strides
// ---------------------------------------------------------------------------
__global__ void prep_weights(const float* __restrict__ Wa1, const float* __restrict__ We1,
                             const float* __restrict__ We2) {
    int i = blockIdx.x * 256 + threadIdx.x;
    float v;
    __half* ph;
    int idx;
    if (i < 128 * SA1) {
        int n = i / SA1, c = i % SA1;
        v = (c < KE) ? Wa1[c * HID + n] : 0.f;
        ph = g_Wa1h; idx = i;
    } else if (i < 2 * 128 * SA1) {
        int j = i - 128 * SA1;
        int n = j / SA1, c = j % SA1;
        v = (c < KE) ? We1[c * HID + n] : 0.f;
        ph = g_We1h; idx = j;
    } else if (i < 2 * 128 * SA1 + 64 * SH3) {
        int j = i - 2 * 128 * SA1;
        int n = j / SH3, c = j % SH3;
        v = (c < HID) ? We2[c * EOUT + n] : 0.f;
        ph = g_We2h; idx = j;
    } else return;
    ph[idx] = __float2half_rn(v);
}

__global__ void init_kernel() {
    int i = blockIdx.x * blockDim.x + threadIdx.x;
    if (i < NN) { g_segmax[i] = 0u; g_denom[i] = 0.f; }
    if (i < NN * EOUT) g_agg[i] = 0.f;
}

// ---------------------------------------------------------------------------
// edge kernel: 128 edges/CTA, 256 threads (8 warps = 4m x 2n)
// ---------------------------------------------------------------------------
#define OFF_IDX  0u           // 256 int
#define OFF_BE1  1024u        // 128 f
#define OFF_BA1  1536u
#define OFF_WA2  2048u
#define OFF_BE2  2560u        // 64 f
#define OFF_LOG  2816u        // 256 f
#define OFF_AH   4096u        // 128*200*2 = 51200
#define OFF_AL   (OFF_AH + 51200u)
#define OFF_BH   (OFF_AL + 51200u)
#define SMEM_E   (OFF_BH + 51200u)   // 157696

__global__ void __launch_bounds__(256) edge_hmma_kernel(
    const float* __restrict__ nf, const float* __restrict__ ef,
    const int* __restrict__ src, const int* __restrict__ dst,
    const float* __restrict__ be1, const float* __restrict__ ba1,
    const float* __restrict__ Wa2, const float* __restrict__ ba2,
    const float* __restrict__ be2, float* __restrict__ uhe)
{
    extern __shared__ __align__(1024) unsigned char smem[];
    const uint32_t sb = smem_u32(smem);
    const int t = threadIdx.x, w = t >> 5, lane = t & 31;
    const int e0 = blockIdx.x * 128;
    const int wm = w >> 1, wn = w & 1;
    const int m_base = wm * 32;

    int*   sIdx = (int*)(smem + OFF_IDX);
    float* sBe1 = (float*)(smem + OFF_BE1);
    float* sBa1 = (float*)(smem + OFF_BA1);
    float* sWa2 = (float*)(smem + OFF_WA2);
    float* sBe2 = (float*)(smem + OFF_BE2);
    float* sLog = (float*)(smem + OFF_LOG);

    if (t < 128) { sBe1[t] = be1[t]; sBa1[t] = ba1[t]; sWa2[t] = Wa2[t]; sIdx[t] = src[e0 + t]; }
    else { sIdx[t] = dst[e0 + t - 128]; if (t < 192) sBe2[t - 128] = be2[t - 128]; }
    __syncthreads();

    // zero A pad cols 160..199 (both images)
    for (int idx = t; idx < 2560; idx += 256) {
        int r = idx / 20, c = 160 + (idx % 20) * 2;
        uint32_t off = (uint32_t)(r * SA1 + c) * 2u;
        *(uint32_t*)(smem + OFF_AH + off) = 0u;
        *(uint32_t*)(smem + OFF_AL + off) = 0u;
    }
    // gather e_in -> A hi/lo (128 x 40 float4)
#pragma unroll
    for (int i = 0; i < 20; i++) {
        int f = t + i * 256;
        int m = f / 40, p = f % 40;
        float4 v;
        if (p < 16)       v = ((const float4*)(nf + (size_t)sIdx[m] * DIN))[p];
        else if (p < 32)  v = ((const float4*)(nf + (size_t)sIdx[128 + m] * DIN))[p - 16];
        else              v = ((const float4*)(ef + (size_t)(e0 + m) * EIN))[p - 32];
        uint32_t h01, l01, h23, l23;
        split2(v.x, v.y, h01, l01);
        split2(v.z, v.w, h23, l23);
        uint32_t off = (uint32_t)(m * SA1 + p * 4) * 2u;
        *(uint2*)(smem + OFF_AH + off) = make_uint2(h01, h23);
        *(uint2*)(smem + OFF_AL + off) = make_uint2(l01, l23);
    }
    // copy Wa1 image (3200 uint4)
    for (int idx = t; idx < 3200; idx += 256)
        ((uint4*)(smem + OFF_BH))[idx] = ((const uint4*)g_Wa1h)[idx];
    __syncthreads();

    // lane-adjusted base addresses
    const uint32_t laneA1 = (uint32_t)(((lane & 15) * SA1 + (lane >> 4) * 8) * 2);
    const uint32_t laneA3 = (uint32_t)(((lane & 15) * SH3 + (lane >> 4) * 8) * 2);
    // B x4 n-pair addressing: lanes 0-7:(n,k0) 8-15:(n,k8) 16-23:(n+8,k0) 24-31:(n+8,k8)
    const uint32_t laneB1 = (uint32_t)((((lane & 7) + ((lane >> 4) << 3)) * SA1
                                        + (((lane >> 3) & 1) * 8)) * 2);
    const uint32_t laneB3 = (uint32_t)((((lane & 7) + ((lane >> 4) << 3)) * SH3
                                        + (((lane >> 3) & 1) * 8)) * 2);
    const uint32_t aHb = sb + OFF_AH + (uint32_t)(m_base * SA1) * 2u + laneA1;
    const uint32_t aLb = sb + OFF_AL + (uint32_t)(m_base * SA1) * 2u + laneA1;

    // ---------------- phase 1: attention hidden + logits ----------------
    {
        const int n_base = wn * 64;
        float C[2][8][4];
#pragma unroll
        for (int ms = 0; ms < 2; ms++)
#pragma unroll
            for (int n = 0; n < 8; n++)
#pragma unroll
                for (int j = 0; j < 4; j++) C[ms][n][j] = 0.f;
        uint32_t bHb = sb + OFF_BH + (uint32_t)(n_base * SA1) * 2u + laneB1;
        gemm2<12, 8, SA1, SA1>(C, aHb, aLb, bHb);
        // logit partials
#pragma unroll
        for (int ms = 0; ms < 2; ms++) {
            float p0 = 0.f, p1 = 0.f;
#pragma unroll
            for (int n = 0; n < 8; n++) {
                int col = n_base + n * 8 + (lane & 3) * 2;
                float w0 = sWa2[col], w1 = sWa2[col + 1];
                float b0 = sBa1[col], b1 = sBa1[col + 1];
                p0 += fmaxf(C[ms][n][0] + b0, 0.f) * w0 + fmaxf(C[ms][n][1] + b1, 0.f) * w1;
                p1 += fmaxf(C[ms][n][2] + b0, 0.f) * w0 + fmaxf(C[ms][n][3] + b1, 0.f) * w1;
            }
            p0 += __shfl_xor_sync(0xffffffffu, p0, 1);
            p0 += __shfl_xor_sync(0xffffffffu, p0, 2);
            p1 += __shfl_xor_sync(0xffffffffu, p1, 1);
            p1 += __shfl_xor_sync(0xffffffffu, p1, 2);
            if ((lane & 3) == 0) {
                int r = m_base + ms * 16 + (lane >> 2);
                sLog[wn * 128 + r] = p0;
                sLog[wn * 128 + r + 8] = p1;
            }
        }
    }
    __syncthreads();   // sLog done; all warps done reading sB (Wa1)

    if (t < 128) {
        float lg = sLog[t] + sLog[128 + t] + ba2[0];
        g_logit[e0 + t] = lg;
        atomicMax(&g_segmax[sIdx[128 + t]], fkey(lg));
    }
    // copy We1 image
    for (int idx = t; idx < 3200; idx += 256)
        ((uint4*)(smem + OFF_BH))[idx] = ((const uint4*)g_We1h)[idx];
    __syncthreads();

    // ---------------- phase 2: edge-MLP hidden ----------------
    {
        const int n_base = wn * 64;
        float C[2][8][4];
#pragma unroll
        for (int ms = 0; ms < 2; ms++)
#pragma unroll
            for (int n = 0; n < 8; n++)
#pragma unroll
                for (int j = 0; j < 4; j++) C[ms][n][j] = 0.f;
        uint32_t bHb = sb + OFF_BH + (uint32_t)(n_base * SA1) * 2u + laneB1;
        gemm2<12, 8, SA1, SA1>(C, aHb, aLb, bHb);
        __syncthreads();   // everyone finished reading sA (e_in) and sB (We1)
        // H = relu(C + be1) -> fp16 hi/lo into A region (stride 136)
#pragma unroll
        for (int ms = 0; ms < 2; ms++) {
            int r0 = m_base + ms * 16 + (lane >> 2), r1 = r0 + 8;
#pragma unroll
            for (int n = 0; n < 8; n++) {
                int col = n_base + n * 8 + (lane & 3) * 2;
                float b0 = sBe1[col], b1 = sBe1[col + 1];
                float x0 = fmaxf(C[ms][n][0] + b0, 0.f), x1 = fmaxf(C[ms][n][1] + b1, 0.f);
                float x2 = fmaxf(C[ms][n][2] + b0, 0.f), x3 = fmaxf(C[ms][n][3] + b1, 0.f);
                uint32_t h, l;
                split2(x0, x1, h, l);
                uint32_t off0 = (uint32_t)(r0 * SH3 + col) * 2u;
                *(uint32_t*)(smem + OFF_AH + off0) = h;
                *(uint32_t*)(smem + OFF_AL + off0) = l;
                split2(x2, x3, h, l);
                uint32_t off1 = (uint32_t)(r1 * SH3 + col) * 2u;
                *(uint32_t*)(smem + OFF_AH + off1) = h;
                *(uint32_t*)(smem + OFF_AL + off1) = l;
            }
        }
    }
    // copy We2 image (1088 uint4)
    for (int idx = t; idx < 1088; idx += 256)
        ((uint4*)(smem + OFF_BH))[idx] = ((const uint4*)g_We2h)[idx];
    __syncthreads();

    // ---------------- phase 3: uh_e = H @ We2 + be2 ----------------
    {
        const int n_base = wn * 32;
        float C[2][4][4];
#pragma unroll
        for (int ms = 0; ms < 2; ms++)
#pragma unroll
            for (int n = 0; n < 4; n++)
#pragma unroll
                for (int j = 0; j < 4; j++) C[ms][n][j] = 0.f;
        uint32_t aH3 = sb + OFF_AH + (uint32_t)(m_base * SH3) * 2u + laneA3;
        uint32_t aL3 = sb + OFF_AL + (uint32_t)(m_base * SH3) * 2u + laneA3;
        uint32_t bH3 = sb + OFF_BH + (uint32_t)(n_base * SH3) * 2u + laneB3;
        gemm2<8, 4, SH3, SH3>(C, aH3, aL3, bH3);
#pragma unroll
        for (int ms = 0; ms < 2; ms++) {
            int r0 = m_base + ms * 16 + (lane >> 2), r1 = r0 + 8;
#pragma unroll
            for (int n = 0; n < 4; n++) {
                int col = n_base + n * 8 + (lane & 3) * 2;
                float b0 = sBe2[col], b1 = sBe2[col + 1];
                float2 o0 = make_float2(C[ms][n][0] + b0, C[ms][n][1] + b1);
                float2 o1 = make_float2(C[ms][n][2] + b0, C[ms][n][3] + b1);
                *(float2*)(uhe + (size_t)(e0 + r0) * 64 + col) = o0;
                *(float2*)(uhe + (size_t)(e0 + r1) * 64 + col) = o1;
            }
        }
    }
}

// ---------------------------------------------------------------------------
__global__ void softmax_denom_kernel(const int* __restrict__ dst) {
    int e = blockIdx.x * 256 + threadIdx.x;
    if (e >= NE) return;
    int d = dst[e];
    float m = funkey(g_segmax[d]);
    float ex = expf(g_logit[e] - m);
    g_ex[e] = ex;
    atomicAdd(&g_denom[d], ex);
}

__global__ void aggregate_kernel(const int* __restrict__ dst,
                                 const float* __restrict__ uhe) {
    int idx = blockIdx.x * 256 + threadIdx.x;   // NE*16 threads exactly
    int e = idx >> 4, q = idx & 15;
    int d = dst[e];
    float attn = g_ex[e] / fmaxf(g_denom[d], 1e-38f);
    float4 u = ((const float4*)(uhe + (size_t)e * EOUT))[q];
    float* a = g_agg + (size_t)d * EOUT + q * 4;
    asm volatile("red.global.add.v2.f32 [%0], {%1,%2};"
                 :: "l"(a), "f"(u.x * attn), "f"(u.y * attn) : "memory");
    asm volatile("red.global.add.v2.f32 [%0], {%1,%2};"
                 :: "l"(a + 2), "f"(u.z * attn), "f"(u.w * attn) : "memory");
}

// ---------------------------------------------------------------------------
// node FFMA path (small: ~1.2 G-MAC)
// ---------------------------------------------------------------------------
template <int K>
__device__ __forceinline__ void layer1_tile(
    const float* __restrict__ W, const float* __restrict__ sX,
    float* __restrict__ sW, float* __restrict__ sH,
    const float* __restrict__ sB, int t)
{
    const int nb = t & 31, mb = t >> 5;
    const int n0 = nb * 4, m0 = mb * 8;
    float acc[8][4];
#pragma unroll
    for (int i = 0; i < 8; i++)
#pragma unroll
        for (int j = 0; j < 4; j++) acc[i][j] = 0.f;
    for (int kc = 0; kc < K; kc += 32) {
        __syncthreads();
#pragma unroll
        for (int i = 0; i < 4; i++) {
            int f = t + i * 256, r = f >> 5, c = f & 31;
            ((float4*)sW)[f] = ((const float4*)(W + (size_t)(kc + r) * HID))[c];
        }
        __syncthreads();
#pragma unroll
        for (int k0 = 0; k0 < 32; k0 += 4) {
            float4 w0 = *(const float4*)(sW + (k0 + 0) * HID + n0);
            float4 w1 = *(const float4*)(sW + (k0 + 1) * HID + n0);
            float4 w2 = *(const float4*)(sW + (k0 + 2) * HID + n0);
            float4 w3 = *(const float4*)(sW + (k0 + 3) * HID + n0);
#pragma unroll
            for (int i = 0; i < 8; i++) {
                float4 xv = *(const float4*)(sX + (m0 + i) * K + kc + k0);
                acc[i][0] += xv.x * w0.x + xv.y * w1.x + xv.z * w2.x + xv.w * w3.x;
                acc[i][1] += xv.x * w0.y + xv.y * w1.y + xv.z * w2.y + xv.w * w3.y;
                acc[i][2] += xv.x * w0.z + xv.y * w1.z + xv.z * w2.z + xv.w * w3.z;
                acc[i][3] += xv.x * w0.w + xv.y * w1.w + xv.z * w2.w + xv.w * w3.w;
            }
        }
    }
    const float b0 = sB[n0], b1 = sB[n0+1], b2 = sB[n0+2], b3 = sB[n0+3];
#pragma unroll
    for (int i = 0; i < 8; i++) {
        float4 h;
        h.x = fmaxf(acc[i][0] + b0, 0.f); h.y = fmaxf(acc[i][1] + b1, 0.f);
        h.z = fmaxf(acc[i][2] + b2, 0.f); h.w = fmaxf(acc[i][3] + b3, 0.f);
        *(float4*)(sH + (m0 + i) * HID + n0) = h;
    }
    __syncthreads();
}

__device__ __forceinline__ void layer2_tile(
    const float* __restrict__ W, const float* __restrict__ sH,
    float* __restrict__ sW, const float* __restrict__ sB,
    float* __restrict__ gout, int row_base, int valid_rows, int t)
{
    const int nb = t & 15, mb = t >> 4;
    const int n0 = nb * 4, m0 = mb * 4;
    float acc[4][4];
#pragma unroll
    for (int i = 0; i < 4; i++)
#pragma unroll
        for (int j = 0; j < 4; j++) acc[i][j] = 0.f;
    for (int kc = 0; kc < 128; kc += 32) {
        __syncthreads();
#pragma unroll
        for (int i = 0; i < 2; i++) {
            int f = t + i * 256, r = f >> 4, c = f & 15;
            ((float4*)sW)[f] = ((const float4*)(W + (size_t)(kc + r) * 64))[c];
        }
        __syncthreads();
#pragma unroll
        for (int k0 = 0; k0 < 32; k0 += 4) {
            float4 w0 = *(const float4*)(sW + (k0 + 0) * 64 + n0);
            float4 w1 = *(const float4*)(sW + (k0 + 1) * 64 + n0);
            float4 w2 = *(const float4*)(sW + (k0 + 2) * 64 + n0);
            float4 w3 = *(const float4*)(sW + (k0 + 3) * 64 + n0);
#pragma unroll
            for (int i = 0; i < 4; i++) {
                float4 xv = *(const float4*)(sH + (m0 + i) * HID + kc + k0);
                acc[i][0] += xv.x * w0.x + xv.y * w1.x + xv.z * w2.x + xv.w * w3.x;
                acc[i][1] += xv.x * w0.y + xv.y * w1.y + xv.z * w2.y + xv.w * w3.y;
                acc[i][2] += xv.x * w0.z + xv.y * w1.z + xv.z * w2.z + xv.w * w3.z;
                acc[i][3] += xv.x * w0.w + xv.y * w1.w + xv.z * w2.w + xv.w * w3.w;
            }
        }
    }
    const float b0 = sB[n0], b1 = sB[n0+1], b2 = sB[n0+2], b3 = sB[n0+3];
#pragma unroll
    for (int i = 0; i < 4; i++) {
        if (m0 + i < valid_rows) {
            float4 o;
            o.x = acc[i][0] + b0; o.y = acc[i][1] + b1;
            o.z = acc[i][2] + b2; o.w = acc[i][3] + b3;
            *(float4*)(gout + (size_t)(row_base + m0 + i) * 64 + n0) = o;
        }
    }
    __syncthreads();
}

__global__ void node_kernel(
    const float* __restrict__ nf,
    const float* __restrict__ Wn1, const float* __restrict__ bn1,
    const float* __restrict__ Wn2, const float* __restrict__ bn2,
    float* __restrict__ uhn)
{
    extern __shared__ float fsmem[];
    float* sX  = fsmem;
    float* sW  = sX + 64 * 128;
    float* sH  = sW + 32 * HID;
    float* sB1 = sH + 64 * HID;
    float* sB2 = sB1 + 128;
    const int t = threadIdx.x;
    const int n0b = blockIdx.x * 64;
    if (t < 128) sB1[t] = bn1[t];
    else if (t < 192) sB2[t - 128] = bn2[t - 128];
#pragma unroll
    for (int i = 0; i < 8; i++) {
        int f = t + i * 256, m = f >> 5, p = f & 31;
        int node = n0b + m;
        int nc = node < NN ? node : NN - 1;
        float4 v;
        if (p < 16) v = ((const float4*)(g_agg + (size_t)nc * EOUT))[p];
        else        v = ((const float4*)(nf + (size_t)nc * DIN))[p - 16];
        *(float4*)(sX + m * 128 + p * 4) = v;
    }
    __syncthreads();
    layer1_tile<128>(Wn1, sX, sW, sH, sB1, t);
    layer2_tile(Wn2, sH, sW, sB2, uhn, n0b, NN - n0b, t);
}

// ---------------------------------------------------------------------------
extern "C" void kernel_launch(void* const* d_in, const int* in_sizes, int n_in,
                              void* d_out, int out_size) {
    const float* nf  = (const float*)d_in[0];
    const float* ef  = (const float*)d_in[1];
    const int*   src = (const int*)d_in[2];
    const int*   dst = (const int*)d_in[3];
    const float* We1 = (const float*)d_in[4];
    const float* be1 = (const float*)d_in[5];
    const float* We2 = (const float*)d_in[6];
    const float* be2 = (const float*)d_in[7];
    const float* Wa1 = (const float*)d_in[8];
    const float* ba1 = (const float*)d_in[9];
    const float* Wa2 = (const float*)d_in[10];
    const float* ba2 = (const float*)d_in[11];
    const float* Wn1 = (const float*)d_in[12];
    const float* bn1 = (const float*)d_in[13];
    const float* Wn2 = (const float*)d_in[14];
    const float* bn2 = (const float*)d_in[15];

    float* out = (float*)d_out;
    float* uhn = out;                              // [NN, DOUT]
    float* uhe = out + (size_t)NN * DOUT;          // [NE, EOUT]

    const int SMEM_N = (64 * 128 + 32 * HID + 64 * HID + 128 + 64) * 4;
    cudaFuncSetAttribute(edge_hmma_kernel, cudaFuncAttributeMaxDynamicSharedMemorySize, SMEM_E);
    cudaFuncSetAttribute(node_kernel, cudaFuncAttributeMaxDynamicSharedMemorySize, SMEM_N);

    const int prep_elems = 2 * 128 * SA1 + 64 * SH3;   // 59904
    prep_weights<<<(prep_elems + 255) / 256, 256>>>(Wa1, We1, We2);
    init_kernel<<<(NN * EOUT + 255) / 256, 256>>>();
    edge_hmma_kernel<<<NE / 128, 256, SMEM_E>>>(nf, ef, src, dst,
                                                be1, ba1, Wa2, ba2, be2, uhe);
    softmax_denom_kernel<<<(NE + 255) / 256, 256>>>(dst);
    aggregate_kernel<<<(NE * 16) / 256, 256>>>(dst, uhe);
    node_kernel<<<(NN + 63) / 64, 256, SMEM_N>>>(nf, Wn1, bn1, Wn2, bn2, uhn);
}